// round 3
// baseline (speedup 1.0000x reference)
#include <cuda_runtime.h>
#include <cuda_bf16.h>

// ============================================================================
// FastAsyncGNN: 3-layer GCN
//   deg/dinv -> CSR build (sorted by dst) -> [GEMM -> gather-agg+bias+relu] x2
//   -> final GEMM + bias
// Shapes: N=50000, E=800000, F_IN=128, F_HID=96, F_OUT=40
// ============================================================================

#define NN 50000
#define EE 800000

// -------- scratch (device globals; no allocation allowed) --------
__device__ int   g_deg[NN];        // in-degree + 1 (self loop)
__device__ int   g_cur[NN];        // fill cursors
__device__ int   g_rowptr[NN + 1]; // CSR row pointers (real edges only)
__device__ float g_dinv[NN];       // rsqrt(deg)
__device__ int   g_col[EE];        // src node per CSR slot
__device__ float g_wgt[EE];        // dinv[src]*dinv[dst] per CSR slot
__device__ __align__(16) float g_h[NN * 96];  // GEMM output buffer
__device__ __align__(16) float g_a[NN * 96];  // aggregated/activated buffer

// ============================================================================
// CSR build
// ============================================================================
__global__ void init_kernel() {
    int i = blockIdx.x * blockDim.x + threadIdx.x;
    if (i < NN) { g_deg[i] = 1; g_cur[i] = 0; }
}

__global__ void count_kernel(const int* __restrict__ dst) {
    int e = blockIdx.x * blockDim.x + threadIdx.x;
    if (e < EE) atomicAdd(&g_deg[dst[e]], 1);
}

// single block, 1024 threads: exclusive scan of (deg-1) + dinv
__global__ void scan_kernel() {
    __shared__ int s[1024];
    int tid = threadIdx.x;
    const int per = (NN + 1023) / 1024;  // 49
    int start = tid * per;
    int end = start + per; if (end > NN) end = NN;
    int sum = 0;
    for (int i = start; i < end; i++) sum += g_deg[i] - 1;
    s[tid] = sum;
    __syncthreads();
    for (int off = 1; off < 1024; off <<= 1) {
        int v = s[tid];
        int u = (tid >= off) ? s[tid - off] : 0;
        __syncthreads();
        s[tid] = v + u;
        __syncthreads();
    }
    int run = (tid > 0) ? s[tid - 1] : 0;
    for (int i = start; i < end; i++) {
        g_rowptr[i] = run;
        run += g_deg[i] - 1;
        g_dinv[i] = rsqrtf((float)g_deg[i]);
    }
    if (tid == 1023) g_rowptr[NN] = s[1023];
}

__global__ void fill_kernel(const int* __restrict__ src, const int* __restrict__ dst) {
    int e = blockIdx.x * blockDim.x + threadIdx.x;
    if (e < EE) {
        int sN = src[e];
        int d = dst[e];
        int p = atomicAdd(&g_cur[d], 1);
        int o = g_rowptr[d] + p;
        g_col[o] = sN;
        g_wgt[o] = g_dinv[sN] * g_dinv[d];
    }
}

// ============================================================================
// GEMM: C[n,FO] = A[n,FI] @ W[FI,FO] (+bias)
// A==nullptr -> read from g_a.  C==nullptr -> write to g_h.
// Plain scalar register-tiled SIMT (no inline asm).
// ============================================================================
template <int FI, int FO, int CT, int TN, int RT, int TM, bool BIAS>
__global__ void __launch_bounds__(256)
gemm_kernel(const float* __restrict__ A_, const float* __restrict__ W,
            const float* __restrict__ bias, float* __restrict__ C_, int n) {
    constexpr int BM = RT * TM;  // 64
    constexpr int BK = 32;

    const float* A = A_ ? A_ : (const float*)g_a;
    float* C = C_ ? C_ : (float*)g_h;

    __shared__ float As[BK][BM + 1];  // [kk][row], pad 1 -> conflict-free

    int tid = threadIdx.x;
    int tx = tid % CT;
    int ty = tid / CT;
    int row0 = blockIdx.x * BM;

    float acc[TM][TN];
#pragma unroll
    for (int r = 0; r < TM; r++)
#pragma unroll
        for (int c = 0; c < TN; c++) acc[r][c] = 0.f;

    for (int k0 = 0; k0 < FI; k0 += BK) {
        // stage A tile (transposed into As[kk][row]); 2 float4 per thread
#pragma unroll
        for (int t = 0; t < 2; t++) {
            int q = tid + t * 256;
            int row = q >> 3;
            int c4 = (q & 7) * 4;
            int gr = row0 + row;
            float4 v = make_float4(0.f, 0.f, 0.f, 0.f);
            if (gr < n) v = *(const float4*)(A + (size_t)gr * FI + k0 + c4);
            As[c4 + 0][row] = v.x;
            As[c4 + 1][row] = v.y;
            As[c4 + 2][row] = v.z;
            As[c4 + 3][row] = v.w;
        }
        __syncthreads();

#pragma unroll
        for (int kk = 0; kk < BK; kk++) {
            float av[TM];
#pragma unroll
            for (int r = 0; r < TM; r++) av[r] = As[kk][ty * TM + r];
            const float* wrow = W + (size_t)(k0 + kk) * FO + tx * TN;
            float bv[TN];
#pragma unroll
            for (int c = 0; c < TN; c++) bv[c] = wrow[c];
#pragma unroll
            for (int c = 0; c < TN; c++)
#pragma unroll
                for (int r = 0; r < TM; r++)
                    acc[r][c] = fmaf(av[r], bv[c], acc[r][c]);
        }
        __syncthreads();
    }

    // write back
#pragma unroll
    for (int r = 0; r < TM; r++) {
        int gr = row0 + ty * TM + r;
        if (gr < n) {
            float* crow = C + (size_t)gr * FO + tx * TN;
#pragma unroll
            for (int c = 0; c < TN; c++) {
                float v = acc[r][c];
                if constexpr (BIAS) v += bias[tx * TN + c];
                crow[c] = v;
            }
        }
    }
}

// ============================================================================
// Aggregation: one warp per node; g_a[i] = relu(bias + dinv^2*g_h[i] + sum w*g_h[src])
// FO = 96 (3 floats per lane; each load = one aligned 128B line per warp)
// ============================================================================
__global__ void __launch_bounds__(256)
agg_kernel(const float* __restrict__ bias) {
    int warp = (blockIdx.x * blockDim.x + threadIdx.x) >> 5;
    int lane = threadIdx.x & 31;
    if (warp >= NN) return;
    const float* h = (const float*)g_h;
    float* out = (float*)g_a;
    int i = warp;
    float di = g_dinv[i];
    float self = di * di;
    const float* hi_ = h + (size_t)i * 96;
    float a0 = self * hi_[lane];
    float a1 = self * hi_[lane + 32];
    float a2 = self * hi_[lane + 64];
    int e = g_rowptr[i];
    int fin = g_rowptr[i + 1];
    for (; e < fin; e++) {
        int s = g_col[e];
        float w = g_wgt[e];
        const float* hr = h + (size_t)s * 96;
        a0 = fmaf(w, hr[lane], a0);
        a1 = fmaf(w, hr[lane + 32], a1);
        a2 = fmaf(w, hr[lane + 64], a2);
    }
    float* o = out + (size_t)i * 96;
    o[lane]      = fmaxf(a0 + bias[lane], 0.f);
    o[lane + 32] = fmaxf(a1 + bias[lane + 32], 0.f);
    o[lane + 64] = fmaxf(a2 + bias[lane + 64], 0.f);
}

// ============================================================================
// launch — pure kernel launches only (graph-capture safe)
// ============================================================================
extern "C" void kernel_launch(void* const* d_in, const int* in_sizes, int n_in,
                              void* d_out, int out_size) {
    const float* x    = (const float*)d_in[0];
    const int*   ei   = (const int*)d_in[1];
    const float* W1   = (const float*)d_in[2];
    const float* b1   = (const float*)d_in[3];
    const float* W2   = (const float*)d_in[4];
    const float* b2   = (const float*)d_in[5];
    const float* Wout = (const float*)d_in[6];
    const float* bout = (const float*)d_in[7];
    float* out = (float*)d_out;

    const int* src = ei;       // edge_index[0]
    const int* dst = ei + EE;  // edge_index[1]

    // ---- CSR build ----
    init_kernel<<<(NN + 255) / 256, 256>>>();
    count_kernel<<<(EE + 255) / 256, 256>>>(dst);
    scan_kernel<<<1, 1024>>>();
    fill_kernel<<<(EE + 255) / 256, 256>>>(src, dst);

    const int gemm_blocks = (NN + 63) / 64;
    const int agg_blocks = (NN * 32 + 255) / 256;

    // ---- layer 1: x @ W1 -> g_h ; agg(g_h)+b1, relu -> g_a ----
    gemm_kernel<128, 96, 16, 6, 16, 4, false>
        <<<gemm_blocks, 256>>>(x, W1, nullptr, nullptr, NN);
    agg_kernel<<<agg_blocks, 256>>>(b1);

    // ---- layer 2: g_a @ W2 -> g_h ; agg(g_h)+b2, relu -> g_a ----
    gemm_kernel<96, 96, 16, 6, 16, 4, false>
        <<<gemm_blocks, 256>>>(nullptr, W2, nullptr, nullptr, NN);
    agg_kernel<<<agg_blocks, 256>>>(b2);

    // ---- output projection: g_a @ Wout + bout -> out ----
    gemm_kernel<96, 40, 8, 5, 32, 2, true>
        <<<gemm_blocks, 256>>>(nullptr, Wout, bout, out, NN);
}

// round 5
// speedup vs baseline: 1.1306x; 1.1306x over previous
#include <cuda_runtime.h>
#include <cuda_bf16.h>

// ============================================================================
// FastAsyncGNN: 3-layer GCN
//   deg/dinv -> CSR build (sorted by dst) -> [GEMM -> gather-agg+bias+relu] x2
//   -> final GEMM + bias
// Shapes: N=50000, E=800000, F_IN=128, F_HID=96, F_OUT=40
// ============================================================================

#define NN 50000
#define EE 800000

// -------- scratch (device globals; no allocation allowed) --------
__device__ int   g_deg[NN];        // in-degree + 1 (self loop)
__device__ int   g_cur[NN];        // fill cursors
__device__ int   g_rowptr[NN + 1]; // CSR row pointers (real edges only)
__device__ float g_dinv[NN];       // rsqrt(deg)
__device__ __align__(8)  int2  g_cw[EE];      // (src, wgt-bits) per CSR slot
__device__ __align__(16) float g_h[NN * 96];  // GEMM output buffer
__device__ __align__(16) float g_a[NN * 96];  // aggregated/activated buffer

// ============================================================================
// CSR build
// ============================================================================
__global__ void init_kernel() {
    int i = blockIdx.x * blockDim.x + threadIdx.x;
    if (i < NN) { g_deg[i] = 1; g_cur[i] = 0; }
}

__global__ void count_kernel(const int* __restrict__ dst) {
    int e = blockIdx.x * blockDim.x + threadIdx.x;
    if (e < EE) atomicAdd(&g_deg[dst[e]], 1);
}

// single block, 1024 threads: exclusive scan of (deg-1) + dinv
__global__ void scan_kernel() {
    __shared__ int s[1024];
    int tid = threadIdx.x;
    const int per = (NN + 1023) / 1024;  // 49
    int start = tid * per;
    int end = start + per; if (end > NN) end = NN;
    int sum = 0;
    for (int i = start; i < end; i++) sum += g_deg[i] - 1;
    s[tid] = sum;
    __syncthreads();
    for (int off = 1; off < 1024; off <<= 1) {
        int v = s[tid];
        int u = (tid >= off) ? s[tid - off] : 0;
        __syncthreads();
        s[tid] = v + u;
        __syncthreads();
    }
    int run = (tid > 0) ? s[tid - 1] : 0;
    for (int i = start; i < end; i++) {
        g_rowptr[i] = run;
        run += g_deg[i] - 1;
        g_dinv[i] = rsqrtf((float)g_deg[i]);
    }
    if (tid == 1023) g_rowptr[NN] = s[1023];
}

__global__ void fill_kernel(const int* __restrict__ src, const int* __restrict__ dst) {
    int e = blockIdx.x * blockDim.x + threadIdx.x;
    if (e < EE) {
        int sN = src[e];
        int d = dst[e];
        int p = atomicAdd(&g_cur[d], 1);
        int o = g_rowptr[d] + p;
        g_cw[o] = make_int2(sN, __float_as_int(g_dinv[sN] * g_dinv[d]));
    }
}

// ============================================================================
// GEMM: C[n,FO] = A[n,FI] @ W[FI,FO] (+bias)
// A==nullptr -> read from g_a.  C==nullptr -> write to g_h.
// Both A and W tiles staged in shared memory; scalar FFMA inner loop.
// BM = RT*TM = 128 rows, BK = 32.
// ============================================================================
template <int FI, int FO, int CT, int TN, int RT, int TM, bool BIAS>
__global__ void __launch_bounds__(256)
gemm_kernel(const float* __restrict__ A_, const float* __restrict__ W,
            const float* __restrict__ bias, float* __restrict__ C_, int n) {
    constexpr int BM = RT * TM;  // 128
    constexpr int BK = 32;
    static_assert(CT * RT == 256, "thread shape");
    static_assert(CT * TN == FO, "col coverage");
    static_assert(FO % 4 == 0, "W vec4 staging");

    const float* A = A_ ? A_ : (const float*)g_a;
    float* C = C_ ? C_ : (float*)g_h;

    __shared__ float As[BK][BM + 1];   // [kk][row]
    __shared__ float Ws[BK][FO];       // [kk][col]

    int tid = threadIdx.x;
    int tx = tid % CT;
    int ty = tid / CT;
    int row0 = blockIdx.x * BM;

    float acc[TM][TN];
#pragma unroll
    for (int r = 0; r < TM; r++)
#pragma unroll
        for (int c = 0; c < TN; c++) acc[r][c] = 0.f;

    constexpr int A4 = BM * (BK / 4);   // float4s in A tile (1024)
    constexpr int W4 = BK * (FO / 4);   // float4s in W tile

    for (int k0 = 0; k0 < FI; k0 += BK) {
        // stage A tile (transposed into As[kk][row])
#pragma unroll
        for (int q = tid; q < A4; q += 256) {
            int row = q / (BK / 4);
            int c4 = (q % (BK / 4)) * 4;
            int gr = row0 + row;
            float4 v = make_float4(0.f, 0.f, 0.f, 0.f);
            if (gr < n) v = *(const float4*)(A + (size_t)gr * FI + k0 + c4);
            As[c4 + 0][row] = v.x;
            As[c4 + 1][row] = v.y;
            As[c4 + 2][row] = v.z;
            As[c4 + 3][row] = v.w;
        }
        // stage W tile
#pragma unroll
        for (int q = tid; q < W4; q += 256) {
            int kk = q / (FO / 4);
            int c4 = (q % (FO / 4)) * 4;
            *(float4*)&Ws[kk][c4] = *(const float4*)(W + (size_t)(k0 + kk) * FO + c4);
        }
        __syncthreads();

#pragma unroll
        for (int kk = 0; kk < BK; kk++) {
            float av[TM];
#pragma unroll
            for (int r = 0; r < TM; r++) av[r] = As[kk][ty * TM + r];
            float bv[TN];
#pragma unroll
            for (int c = 0; c < TN; c++) bv[c] = Ws[kk][tx * TN + c];
#pragma unroll
            for (int c = 0; c < TN; c++)
#pragma unroll
                for (int r = 0; r < TM; r++)
                    acc[r][c] = fmaf(av[r], bv[c], acc[r][c]);
        }
        __syncthreads();
    }

    // write back
#pragma unroll
    for (int r = 0; r < TM; r++) {
        int gr = row0 + ty * TM + r;
        if (gr < n) {
            float* crow = C + (size_t)gr * FO + tx * TN;
#pragma unroll
            for (int c = 0; c < TN; c++) {
                float v = acc[r][c];
                if constexpr (BIAS) v += bias[tx * TN + c];
                crow[c] = v;
            }
        }
    }
}

// ============================================================================
// Aggregation: one warp per node; g_a[i] = relu(bias + dinv^2*g_h[i] + sum w*g_h[src])
// 96 feats = 3 floats/lane; each gather row = 3 coalesced 128B lines.
// ============================================================================
__global__ void __launch_bounds__(256)
agg_kernel(const float* __restrict__ bias) {
    int warp = (blockIdx.x * blockDim.x + threadIdx.x) >> 5;
    int lane = threadIdx.x & 31;
    if (warp >= NN) return;
    const float* h = (const float*)g_h;
    float* out = (float*)g_a;
    int i = warp;
    float di = g_dinv[i];
    float self = di * di;
    const float* hi_ = h + (size_t)i * 96;
    float a0 = self * hi_[lane];
    float a1 = self * hi_[lane + 32];
    float a2 = self * hi_[lane + 64];
    int e = g_rowptr[i];
    int fin = g_rowptr[i + 1];
#pragma unroll 4
    for (; e < fin; e++) {
        int2 cw = g_cw[e];
        int s = cw.x;
        float w = __int_as_float(cw.y);
        const float* hr = h + (size_t)s * 96;
        a0 = fmaf(w, hr[lane], a0);
        a1 = fmaf(w, hr[lane + 32], a1);
        a2 = fmaf(w, hr[lane + 64], a2);
    }
    float* o = out + (size_t)i * 96;
    o[lane]      = fmaxf(a0 + bias[lane], 0.f);
    o[lane + 32] = fmaxf(a1 + bias[lane + 32], 0.f);
    o[lane + 64] = fmaxf(a2 + bias[lane + 64], 0.f);
}

// ============================================================================
// launch — pure kernel launches only (graph-capture safe)
// ============================================================================
extern "C" void kernel_launch(void* const* d_in, const int* in_sizes, int n_in,
                              void* d_out, int out_size) {
    const float* x    = (const float*)d_in[0];
    const int*   ei   = (const int*)d_in[1];
    const float* W1   = (const float*)d_in[2];
    const float* b1   = (const float*)d_in[3];
    const float* W2   = (const float*)d_in[4];
    const float* b2   = (const float*)d_in[5];
    const float* Wout = (const float*)d_in[6];
    const float* bout = (const float*)d_in[7];
    float* out = (float*)d_out;

    const int* src = ei;       // edge_index[0]
    const int* dst = ei + EE;  // edge_index[1]

    // ---- CSR build ----
    init_kernel<<<(NN + 255) / 256, 256>>>();
    count_kernel<<<(EE + 255) / 256, 256>>>(dst);
    scan_kernel<<<1, 1024>>>();
    fill_kernel<<<(EE + 255) / 256, 256>>>(src, dst);

    const int gemm_blocks = (NN + 127) / 128;
    const int agg_blocks = (NN * 32 + 255) / 256;

    // ---- layer 1: x @ W1 -> g_h ; agg(g_h)+b1, relu -> g_a ----
    gemm_kernel<128, 96, 16, 6, 16, 8, false>
        <<<gemm_blocks, 256>>>(x, W1, nullptr, nullptr, NN);
    agg_kernel<<<agg_blocks, 256>>>(b1);

    // ---- layer 2: g_a @ W2 -> g_h ; agg(g_h)+b2, relu -> g_a ----
    gemm_kernel<96, 96, 16, 6, 16, 8, false>
        <<<gemm_blocks, 256>>>(nullptr, W2, nullptr, nullptr, NN);
    agg_kernel<<<agg_blocks, 256>>>(b2);

    // ---- output projection: g_a @ Wout + bout -> out ----
    gemm_kernel<96, 40, 8, 5, 32, 4, true>
        <<<gemm_blocks, 256>>>(nullptr, Wout, bout, out, NN);
}